// round 11
// baseline (speedup 1.0000x reference)
#include <cuda_runtime.h>
#include <cuda_bf16.h>
#include <cstdint>

#define BB 8
#define NN 2048
#define DD 64
#define TIM 64               // i-rows per CTA (4 warps x 16)
#define KC 32                // j-chunk
#define NCHUNK (NN / KC)     // 64
#define SPLIT 4
#define CPS (NCHUNK / SPLIT) // 16 chunks per CTA
#define HPITCH 144           // smem H row pitch: conflict-free ldmatrix
#define MPITCH 144           // smem mask row pitch

// ---- dynamic smem layout (bytes) ----
#define MBUF (TIM * MPITCH)              // 9216 per buffer (single mask)
#define HBUF (KC * HPITCH)               // 4608 per buffer
#define SM_M  0                          // [2][MBUF]
#define SM_H  (2 * MBUF)                 // [2][HBUF]
#define SM_T  (SM_H + 2 * HBUF)          // [2][128]
#define SM_V  (SM_T + 2 * 128)           // [2][128]
#define SMEM_TOTAL (SM_V + 2 * 128)      // 28160 -> 6+ CTAs/SM

// ---- device scratch ----
__device__ __nv_bfloat16 g_hb[BB * NN * DD];  // H: [n][d] bf16
__device__ float g_s[BB * NN];
__device__ float g_t[BB * NN];
__device__ float g_u[BB * NN];
__device__ float g_v[BB * NN];
__device__ float g_lam[2 * DD];
// split-K partials
__device__ float g_nA[SPLIT][BB * NN * DD];
__device__ float g_nJ[SPLIT][BB * NN * DD];
__device__ float g_dA[SPLIT][BB * NN];
__device__ float g_dJ[SPLIT][BB * NN];

// ---- PTX helpers (base-target instructions only) ----
__device__ __forceinline__ void mma_bf16(float* d,
    uint32_t a0, uint32_t a1, uint32_t a2, uint32_t a3, uint32_t b0, uint32_t b1) {
    asm volatile(
        "mma.sync.aligned.m16n8k16.row.col.f32.bf16.bf16.f32 "
        "{%0,%1,%2,%3}, {%4,%5,%6,%7}, {%8,%9}, {%0,%1,%2,%3};"
        : "+f"(d[0]), "+f"(d[1]), "+f"(d[2]), "+f"(d[3])
        : "r"(a0), "r"(a1), "r"(a2), "r"(a3), "r"(b0), "r"(b1));
}
__device__ __forceinline__ void ldsm4t(uint32_t& r0, uint32_t& r1, uint32_t& r2, uint32_t& r3, uint32_t addr) {
    asm volatile("ldmatrix.sync.aligned.m8n8.x4.trans.shared.b16 {%0,%1,%2,%3}, [%4];"
        : "=r"(r0), "=r"(r1), "=r"(r2), "=r"(r3) : "r"(addr));
}
__device__ __forceinline__ uint32_t packbf(float lo, float hi) {
    uint32_t r;
    asm("cvt.rn.satfinite.bf16x2.f32 %0, %1, %2;" : "=r"(r) : "f"(hi), "f"(lo));
    return r;
}
#define CP16(dst, src) asm volatile("cp.async.cg.shared.global [%0], [%1], 16;" :: "r"(dst), "l"(src))
#define CP_COMMIT()    asm volatile("cp.async.commit_group;" ::: "memory")
#define CP_WAIT1()     asm volatile("cp.async.wait_group 1;" ::: "memory")
#define CP_WAIT0()     asm volatile("cp.async.wait_group 0;" ::: "memory")

__device__ __forceinline__ float pvsel(float st, float uv) { return (st >= 1.0f) ? st : uv; }

// j-permutation: HMMA k-slot kk (0..15) -> global j within 16-block.
// Lane tq owns k = {2tq, 2tq+1, 2tq+8, 2tq+9} -> j = {4tq..4tq+3} (contiguous).
__device__ __forceinline__ int psi(int kk) {
    return (((kk >> 1) & 3) << 2) + ((kk >> 3) << 1) + (kk & 1);
}

// =====================================================================
// Kernel A: h = feats @ W^T (bf16), exps, lambdas.
// 512 threads = 16 warps; warp = 4 rows; lane = 2 cols x 4 rows.
// =====================================================================
__global__ __launch_bounds__(512) void prep_kernel(
    const float* __restrict__ feats, const float* __restrict__ W,
    const float* __restrict__ attn_src, const float* __restrict__ attn_dst,
    const float* __restrict__ lambda_params)
{
    __shared__ float sWt[DD * 66];   // sWt[d*66+o] = W[o][d]
    __shared__ float sF[64 * DD];    // 64 rows, row-major

    const int t = threadIdx.x;
    const int warp = t >> 5, lane = t & 31;
    const int o = lane * 2;
    const int row0 = blockIdx.x * 64;
    const int rb = warp * 4;

    #pragma unroll
    for (int w = 0; w < 8; ++w) {
        int x = t + 512 * w;
        sWt[(x & 63) * 66 + (x >> 6)] = W[x];
    }
    #pragma unroll
    for (int w = 0; w < 2; ++w) {
        const int x4 = t + 512 * w;
        *(float4*)&sF[x4 * 4] = *(const float4*)(feats + (size_t)row0 * DD + x4 * 4);
    }
    __syncthreads();

    float h[4][2];
    #pragma unroll
    for (int r = 0; r < 4; ++r) { h[r][0] = 0.f; h[r][1] = 0.f; }

    #pragma unroll
    for (int d = 0; d < DD; ++d) {
        const float2 w2 = *(const float2*)&sWt[d * 66 + o];
        #pragma unroll
        for (int r = 0; r < 4; ++r) {
            const float fd = sF[(rb + r) * DD + d];
            h[r][0] = fmaf(fd, w2.x, h[r][0]);
            h[r][1] = fmaf(fd, w2.y, h[r][1]);
        }
    }

    #pragma unroll
    for (int r = 0; r < 4; ++r) {
        *(__nv_bfloat162*)(g_hb + (size_t)(row0 + rb + r) * DD + o) =
            __nv_bfloat162(__float2bfloat16(h[r][0]), __float2bfloat16(h[r][1]));
    }

    const float2 ws = *(const float2*)(attn_src + o);
    const float2 wd = *(const float2*)(attn_dst + o);
    float rs[4], rd[4];
    #pragma unroll
    for (int r = 0; r < 4; ++r) {
        rs[r] = h[r][0] * ws.x + h[r][1] * ws.y;
        rd[r] = h[r][0] * wd.x + h[r][1] * wd.y;
    }
    #pragma unroll
    for (int off = 16; off; off >>= 1) {
        #pragma unroll
        for (int r = 0; r < 4; ++r) {
            rs[r] += __shfl_down_sync(0xffffffffu, rs[r], off);
            rd[r] += __shfl_down_sync(0xffffffffu, rd[r], off);
        }
    }
    if (lane == 0) {
        #pragma unroll
        for (int r = 0; r < 4; ++r) {
            const int n = row0 + rb + r;
            g_s[n] = expf(rs[r]);
            g_u[n] = expf(0.2f * rs[r]);
            g_t[n] = expf(rd[r]);
            g_v[n] = expf(0.2f * rd[r]);
        }
    }
    if (blockIdx.x == 0 && t >= 64 && t < 128) {
        int d = t - 64;
        float l0 = lambda_params[d * 2];
        float l1 = lambda_params[d * 2 + 1];
        float m = fmaxf(l0, l1);
        float e0 = expf(l0 - m), e1 = expf(l1 - m);
        float inv = 1.0f / (e0 + e1);
        g_lam[d] = e0 * inv;
        g_lam[DD + d] = e1 * inv;
    }
}

// =====================================================================
// Kernel B: HMMA masked attention, ONE mask per CTA, split-K, j-permuted
// grid = (NN/TIM=32, BB=8, 2*SPLIT=8): z = sp*2 + maskSel
// 128 threads, target 6 CTAs/SM
// =====================================================================
__global__ __launch_bounds__(128, 6) void attn_hmma_kernel(
    const int* __restrict__ mask_adj, const int* __restrict__ mask_job,
    const int* __restrict__ bidx)
{
    extern __shared__ __align__(16) char smem[];

    const int t = threadIdx.x;
    const int lane = t & 31, wid = t >> 5;
    const int b = blockIdx.y;
    const int z = blockIdx.z;
    const int sp = z >> 1;
    const int isJob = z & 1;
    const int i_base = blockIdx.x * TIM;
    const int bN = b * NN;

    int mb = bidx[b];                 // arange(B) identity gather; clamp defensively
    if (mb < 0 || mb >= BB) mb = b;

    const int* __restrict__ mask = isJob ? mask_job : mask_adj;
    float* __restrict__ nOut = isJob ? g_nJ[sp] : g_nA[sp];
    float* __restrict__ dOut = isJob ? g_dJ[sp] : g_dA[sp];

    const int g  = lane >> 2;
    const int tq = lane & 3;
    const int r0 = wid * 16 + g;      // tile row 0..63
    const int r1 = r0 + 8;

    const float si0 = g_s[bN + i_base + r0], ui0 = g_u[bN + i_base + r0];
    const float si1 = g_s[bN + i_base + r1], ui1 = g_u[bN + i_base + r1];

    const uint32_t sub = (uint32_t)__cvta_generic_to_shared(smem);

    // staging identities
    const int srow = t >> 1, shalf = t & 1;          // masks: 64 rows x 2 halves (64B)
    const int* mSrc = mask + ((size_t)mb * NN + i_base + srow) * NN + shalf * 16;
    const uint32_t mDst = sub + SM_M + srow * MPITCH + shalf * 64;
    const int srowp = (srow & 16) | psi(srow & 15);  // H row permutation
    const char* hSrc = (const char*)(g_hb + ((size_t)(bN + srowp) << 6)) + shalf * 64;
    const uint32_t hDst = sub + SM_H + srow * HPITCH + shalf * 64;

    auto stage = [&](int c, int s) {
        const char* mp = (const char*)(mSrc + c * KC);
        const uint32_t dm = mDst + s * MBUF;
        #pragma unroll
        for (int k = 0; k < 4; ++k) CP16(dm + k * 16, mp + k * 16);
        if (t < 64) {   // H: 32 rows x 128B (row-permuted source)
            const char* hp = hSrc + (size_t)c * KC * 128;
            const uint32_t dh = hDst + s * HBUF;
            CP16(dh,      hp);
            CP16(dh + 16, hp + 16);
            CP16(dh + 32, hp + 32);
            CP16(dh + 48, hp + 48);
        } else if (t < 72) {
            CP16(sub + SM_T + s * 128 + (t - 64) * 16, (const char*)(g_t + bN + c * KC) + (t - 64) * 16);
        } else if (t < 80) {
            CP16(sub + SM_V + s * 128 + (t - 72) * 16, (const char*)(g_v + bN + c * KC) + (t - 72) * 16);
        }
    };

    // ldmatrix per-lane offset (smem row = k index)
    const int mid = lane >> 3, mrow = lane & 7;
    const int lmoff = ((mid & 1) * 8 + mrow) * HPITCH + (mid >> 1) * 16;

    float acc[32];
    #pragma unroll
    for (int q = 0; q < 32; ++q) acc[q] = 0.f;
    float den0 = 0.f, den1 = 0.f;

    const int c0 = sp * CPS;
    stage(c0, 0);
    CP_COMMIT();

    for (int ci = 0; ci < CPS; ++ci) {
        const int c = c0 + ci;
        const int s = ci & 1;
        if (ci + 1 < CPS) {
            stage(c + 1, 1 - s);
            CP_COMMIT();
            CP_WAIT1();
        } else {
            CP_WAIT0();
        }
        __syncthreads();

        const char* mS = smem + SM_M + s * MBUF;
        const uint32_t hbase = sub + SM_H + s * HBUF + lmoff;
        const float* sTs = (const float*)(smem + SM_T + s * 128);
        const float* sVs = (const float*)(smem + SM_V + s * 128);

        #pragma unroll
        for (int kt = 0; kt < 2; ++kt) {
            const int mo = kt * 64 + tq * 16;         // one int4: j = 16kt + 4tq + 0..3
            const int4 m0 = *(const int4*)(mS + r0 * MPITCH + mo);
            const int4 m1 = *(const int4*)(mS + r1 * MPITCH + mo);

            const float4 t4 = *(const float4*)&sTs[kt * 16 + 4 * tq];
            const float4 v4 = *(const float4*)&sVs[kt * 16 + 4 * tq];

            // pv per (row, j): exp(leaky(e)) = st if st>=1 else uv
            const float A00 = m0.x ? pvsel(si0 * t4.x, ui0 * v4.x) : 0.f;
            const float A01 = m0.y ? pvsel(si0 * t4.y, ui0 * v4.y) : 0.f;
            const float A02 = m0.z ? pvsel(si0 * t4.z, ui0 * v4.z) : 0.f;
            const float A03 = m0.w ? pvsel(si0 * t4.w, ui0 * v4.w) : 0.f;
            const float A10 = m1.x ? pvsel(si1 * t4.x, ui1 * v4.x) : 0.f;
            const float A11 = m1.y ? pvsel(si1 * t4.y, ui1 * v4.y) : 0.f;
            const float A12 = m1.z ? pvsel(si1 * t4.z, ui1 * v4.z) : 0.f;
            const float A13 = m1.w ? pvsel(si1 * t4.w, ui1 * v4.w) : 0.f;

            den0 += (A00 + A01) + (A02 + A03);
            den1 += (A10 + A11) + (A12 + A13);

            // A-frag: a0 = (k=2tq, 2tq+1) -> j 4tq,4tq+1; a2 = (k+8) -> j 4tq+2,4tq+3
            const uint32_t a0 = packbf(A00, A01), a1 = packbf(A10, A11);
            const uint32_t a2 = packbf(A02, A03), a3 = packbf(A12, A13);

            const uint32_t hb = hbase + kt * (16 * HPITCH);
            #pragma unroll
            for (int np = 0; np < 4; ++np) {
                uint32_t b0, b1, b2, b3;
                ldsm4t(b0, b1, b2, b3, hb + np * 32);
                mma_bf16(&acc[(2 * np) * 4],     a0, a1, a2, a3, b0, b1);
                mma_bf16(&acc[(2 * np + 1) * 4], a0, a1, a2, a3, b2, b3);
            }
        }
        __syncthreads();
    }

    // denominator butterfly over the 4 lanes sharing g
    den0 += __shfl_xor_sync(0xffffffffu, den0, 1);
    den0 += __shfl_xor_sync(0xffffffffu, den0, 2);
    den1 += __shfl_xor_sync(0xffffffffu, den1, 1);
    den1 += __shfl_xor_sync(0xffffffffu, den1, 2);

    // write partials
    const size_t o0b = (size_t)(bN + i_base + r0) << 6;
    const size_t o1b = (size_t)(bN + i_base + r1) << 6;
    #pragma unroll
    for (int n = 0; n < 8; ++n) {
        const int cc = n * 8 + 2 * tq;
        *(float2*)(nOut + o0b + cc) = make_float2(acc[n * 4 + 0], acc[n * 4 + 1]);
        *(float2*)(nOut + o1b + cc) = make_float2(acc[n * 4 + 2], acc[n * 4 + 3]);
    }
    if (tq == 0) {
        dOut[bN + i_base + r0] = den0;
        dOut[bN + i_base + r1] = den1;
    }
}

// =====================================================================
// Kernel C: combine splits, normalize, blend, residual
// =====================================================================
__global__ __launch_bounds__(256) void combine_kernel(
    const float* __restrict__ feats, float* __restrict__ out)
{
    const int idx = (blockIdx.x * blockDim.x + threadIdx.x) * 4;
    const int n = idx >> 6;
    const int d = idx & 63;

    float4 na = make_float4(0.f, 0.f, 0.f, 0.f);
    float4 nj = make_float4(0.f, 0.f, 0.f, 0.f);
    float da = 0.f, dj = 0.f;
    #pragma unroll
    for (int sp = 0; sp < SPLIT; ++sp) {
        const float4 a = *(const float4*)(g_nA[sp] + idx);
        const float4 j = *(const float4*)(g_nJ[sp] + idx);
        na.x += a.x; na.y += a.y; na.z += a.z; na.w += a.w;
        nj.x += j.x; nj.y += j.y; nj.z += j.z; nj.w += j.w;
        da += g_dA[sp][n];
        dj += g_dJ[sp][n];
    }
    const float ra = 1.0f / da;
    const float rj = 1.0f / dj;
    const float4 lA = *(const float4*)&g_lam[d];
    const float4 lJ = *(const float4*)&g_lam[DD + d];
    const float4 f = *(const float4*)(feats + idx);
    float4 o;
    o.x = lA.x * na.x * ra + lJ.x * nj.x * rj + f.x;
    o.y = lA.y * na.y * ra + lJ.y * nj.y * rj + f.y;
    o.z = lA.z * na.z * ra + lJ.z * nj.z * rj + f.z;
    o.w = lA.w * na.w * ra + lJ.w * nj.w * rj + f.w;
    *(float4*)(out + idx) = o;
}

extern "C" void kernel_launch(void* const* d_in, const int* in_sizes, int n_in,
                              void* d_out, int out_size) {
    (void)in_sizes; (void)n_in; (void)out_size;
    const int*   mask_adj      = (const int*)d_in[0];
    const int*   mask_job      = (const int*)d_in[1];
    const int*   bidx          = (const int*)d_in[2];
    const float* feats         = (const float*)d_in[3];
    const float* W             = (const float*)d_in[4];
    const float* attn_src      = (const float*)d_in[5];
    const float* attn_dst      = (const float*)d_in[6];
    const float* lambda_params = (const float*)d_in[7];
    float* out = (float*)d_out;

    prep_kernel<<<BB * NN / 64, 512>>>(feats, W, attn_src, attn_dst, lambda_params);
    attn_hmma_kernel<<<dim3(NN / TIM, BB, 2 * SPLIT), 128, SMEM_TOTAL>>>(mask_adj, mask_job, bidx);
    combine_kernel<<<BB * NN * DD / 4 / 256, 256>>>(feats, out);
}